// round 13
// baseline (speedup 1.0000x reference)
#include <cuda_runtime.h>
#include <math.h>

typedef unsigned long long u64;

#define NMAX 50000
#define EMAX 800000
#define C 128

// ---------------- scratch (static __device__, no allocation) ----------------
__device__ int    g_cnt [NMAX];
__device__ int    g_fill[NMAX];
__device__ int    g_ptr [NMAX + 1];
__device__ int    g_ecol[EMAX];
__device__ float4 g_nn  [NMAX];        // {n_cos, q_eud, p_eud, 0}
__device__ float  g_aggc[NMAX * C];
__device__ float  g_agge[NMAX * C];
__device__ float  g_x1  [NMAX * C];
__device__ float  g_x2  [NMAX * C];
__device__ float  g_scores[NMAX * 4];

// ---------------- packed fp32x2 helpers (SASS FFMA2) ----------------
__device__ __forceinline__ void ffma2(u64& d, u64 a, u64 b) {
    asm("fma.rn.f32x2 %0, %1, %2, %0;" : "+l"(d) : "l"(a), "l"(b));
}
__device__ __forceinline__ float lo32(u64 v) { return __uint_as_float((unsigned)v); }
__device__ __forceinline__ float hi32(u64 v) { return __uint_as_float((unsigned)(v >> 32)); }

// ---------------- CSR build ----------------
__global__ void zero_cnt_kernel(int N) {
    int i = blockIdx.x * blockDim.x + threadIdx.x;
    if (i < N) g_cnt[i] = 0;
}

__global__ void hist_kernel(const int* __restrict__ row, int E) {
    int i = blockIdx.x * blockDim.x + threadIdx.x;
    if (i < E) atomicAdd(&g_cnt[row[i]], 1);
}

__global__ void scan_kernel(int N) {
    __shared__ int sums[1024];
    int t = threadIdx.x;
    int chunk = (N + 1023) >> 10;
    int start = t * chunk;
    int end = min(start + chunk, N);
    int s = 0;
    for (int i = start; i < end; i++) s += g_cnt[i];
    sums[t] = s;
    __syncthreads();
    for (int off = 1; off < 1024; off <<= 1) {
        int v = (t >= off) ? sums[t - off] : 0;
        __syncthreads();
        sums[t] += v;
        __syncthreads();
    }
    int base = sums[t] - s;
    for (int i = start; i < end; i++) {
        g_ptr[i]  = base;
        g_fill[i] = base;
        base += g_cnt[i];
    }
    if (t == 0) g_ptr[N] = sums[1023];
}

__global__ void fill_kernel(const int* __restrict__ row, const int* __restrict__ col, int E) {
    int i = blockIdx.x * blockDim.x + threadIdx.x;
    if (i < E) {
        int r = row[i];
        int p = atomicAdd(&g_fill[r], 1);
        g_ecol[p] = col[i];
    }
}

// ---------------- per-node stats: {n(cos-matrix), q, p} with q/p = n_e^2 -/+ 2*eps*sum ----------------
// Pass 1: cos and eud both use x.
__global__ void norm1_kernel(const float* __restrict__ X, int N) {
    int node = blockIdx.x * 8 + (threadIdx.x >> 5);
    int lane = threadIdx.x & 31;
    if (node >= N) return;
    float4 v = ((const float4*)X)[node * 32 + lane];
    float ss = v.x * v.x + v.y * v.y + v.z * v.z + v.w * v.w;
    float sm = v.x + v.y + v.z + v.w;
    #pragma unroll
    for (int o = 16; o; o >>= 1) {
        ss += __shfl_xor_sync(0xffffffffu, ss, o);
        sm += __shfl_xor_sync(0xffffffffu, sm, o);
    }
    if (lane == 0)
        g_nn[node] = make_float4(sqrtf(ss), ss - 2e-6f * sm, ss + 2e-6f * sm, 0.f);
}

// Pass 2: cos uses x3, eud uses x4.
__global__ void norm2_kernel(const float* __restrict__ X3, const float* __restrict__ X4, int N) {
    int node = blockIdx.x * 8 + (threadIdx.x >> 5);
    int lane = threadIdx.x & 31;
    if (node >= N) return;
    float4 a = ((const float4*)X3)[node * 32 + lane];
    float4 b = ((const float4*)X4)[node * 32 + lane];
    float s3 = a.x * a.x + a.y * a.y + a.z * a.z + a.w * a.w;
    float s4 = b.x * b.x + b.y * b.y + b.z * b.z + b.w * b.w;
    float m4 = b.x + b.y + b.z + b.w;
    #pragma unroll
    for (int o = 16; o; o >>= 1) {
        s3 += __shfl_xor_sync(0xffffffffu, s3, o);
        s4 += __shfl_xor_sync(0xffffffffu, s4, o);
        m4 += __shfl_xor_sync(0xffffffffu, m4, o);
    }
    if (lane == 0)
        g_nn[node] = make_float4(sqrtf(s3), s4 - 2e-6f * m4, s4 + 2e-6f * m4, 0.f);
}

// ---------------- edge pass 1: single reduction + prefetch pipeline ----------------
__global__ void edge1_kernel(const float* __restrict__ X, int N) {
    int node = blockIdx.x * 8 + (threadIdx.x >> 5);
    int lane = threadIdx.x & 31;
    if (node >= N) return;
    const float4* X4 = (const float4*)X;
    float4 xi = X4[node * 32 + lane];
    float4 me = g_nn[node];
    float ni = me.x, pi = me.z;
    int s = g_ptr[node], e = g_ptr[node + 1];
    float4 ac = make_float4(0.f, 0.f, 0.f, 0.f);
    float4 ae = make_float4(0.f, 0.f, 0.f, 0.f);
    if (s < e) {
        int c0 = __ldg(&g_ecol[s]);
        float4 xc = __ldg(&X4[c0 * 32 + lane]);
        float2 nq = __ldg((const float2*)&g_nn[c0]);
        for (int j = s; j < e; j++) {
            int jn = (j + 1 < e) ? j + 1 : j;
            int cn = __ldg(&g_ecol[jn]);
            float4 xcn = __ldg(&X4[cn * 32 + lane]);
            float2 nqn = __ldg((const float2*)&g_nn[cn]);
            float d = xi.x * xc.x + xi.y * xc.y + xi.z * xc.z + xi.w * xc.w;
            #pragma unroll
            for (int o = 16; o; o >>= 1) d += __shfl_xor_sync(0xffffffffu, d, o);
            float ecos = d / fmaxf(ni * nq.x, 1e-8f);
            float eeud = sqrtf(fmaxf(pi + nq.y - 2.f * d + 1.28e-10f, 0.f));
            ac.x += ecos * xc.x; ac.y += ecos * xc.y; ac.z += ecos * xc.z; ac.w += ecos * xc.w;
            ae.x += eeud * xc.x; ae.y += eeud * xc.y; ae.z += eeud * xc.z; ae.w += eeud * xc.w;
            xc = xcn; nq = nqn;
        }
    }
    float inv = 1.0f / fmaxf((float)(e - s), 1.0f);
    ac.x *= inv; ac.y *= inv; ac.z *= inv; ac.w *= inv;
    ae.x *= inv; ae.y *= inv; ae.z *= inv; ae.w *= inv;
    ((float4*)g_aggc)[node * 32 + lane] = ac;
    ((float4*)g_agge)[node * 32 + lane] = ae;
}

// ---------------- edge pass 2: cos on x3, eud on x4 (dot-form) + prefetch pipeline ----------------
__global__ void edge2_kernel(const float* __restrict__ X3, const float* __restrict__ X4, int N) {
    int node = blockIdx.x * 8 + (threadIdx.x >> 5);
    int lane = threadIdx.x & 31;
    if (node >= N) return;
    const float4* A4 = (const float4*)X3;
    const float4* B4 = (const float4*)X4;
    float4 x3i = A4[node * 32 + lane];
    float4 x4i = B4[node * 32 + lane];
    float4 me = g_nn[node];
    float n3 = me.x, p4 = me.z;
    int s = g_ptr[node], e = g_ptr[node + 1];
    float4 ac = make_float4(0.f, 0.f, 0.f, 0.f);
    float4 ae = make_float4(0.f, 0.f, 0.f, 0.f);
    if (s < e) {
        int c0 = __ldg(&g_ecol[s]);
        float4 xc3 = __ldg(&A4[c0 * 32 + lane]);
        float4 xc4 = __ldg(&B4[c0 * 32 + lane]);
        float2 nq = __ldg((const float2*)&g_nn[c0]);
        for (int j = s; j < e; j++) {
            int jn = (j + 1 < e) ? j + 1 : j;
            int cn = __ldg(&g_ecol[jn]);
            float4 xc3n = __ldg(&A4[cn * 32 + lane]);
            float4 xc4n = __ldg(&B4[cn * 32 + lane]);
            float2 nqn = __ldg((const float2*)&g_nn[cn]);
            float d3 = x3i.x * xc3.x + x3i.y * xc3.y + x3i.z * xc3.z + x3i.w * xc3.w;
            float d4 = x4i.x * xc4.x + x4i.y * xc4.y + x4i.z * xc4.z + x4i.w * xc4.w;
            #pragma unroll
            for (int o = 16; o; o >>= 1) {
                d3 += __shfl_xor_sync(0xffffffffu, d3, o);
                d4 += __shfl_xor_sync(0xffffffffu, d4, o);
            }
            float ecos = d3 / fmaxf(n3 * nq.x, 1e-8f);
            float eeud = sqrtf(fmaxf(p4 + nq.y - 2.f * d4 + 1.28e-10f, 0.f));
            ac.x += ecos * xc3.x; ac.y += ecos * xc3.y; ac.z += ecos * xc3.z; ac.w += ecos * xc3.w;
            ae.x += eeud * xc4.x; ae.y += eeud * xc4.y; ae.z += eeud * xc4.z; ae.w += eeud * xc4.w;
            xc3 = xc3n; xc4 = xc4n; nq = nqn;
        }
    }
    float inv = 1.0f / fmaxf((float)(e - s), 1.0f);
    ac.x *= inv; ac.y *= inv; ac.z *= inv; ac.w *= inv;
    ae.x *= inv; ae.y *= inv; ae.z *= inv; ae.w *= inv;
    ((float4*)g_aggc)[node * 32 + lane] = ac;
    ((float4*)g_agge)[node * 32 + lane] = ae;
}

// ==================== GEMM kernels (unchanged from R7) ====================

// ---------------- layer 0: x3 = relu(aggc@Wl + x@Wr + b), x4 = relu(agge@Wl + x@Wr + b) ----------------
__global__ void layer0_kernel(const float* __restrict__ X,
                              const float* __restrict__ Wl, const float* __restrict__ Wr,
                              const float* __restrict__ bias,
                              float* __restrict__ O3, float* __restrict__ O4, int M) {
    __shared__ __align__(16) float sAc[64][36], sAe[64][36], sAx[64][36];
    __shared__ __align__(16) float sBl[16][128], sBr[16][128];
    int tid = threadIdx.x;
    int tx = tid & 15, ty = tid >> 4;
    int row0 = blockIdx.x * 64;
    u64 accC[4][4], accE[4][4], accX[4][4];
    #pragma unroll
    for (int i = 0; i < 4; i++)
        #pragma unroll
        for (int j = 0; j < 4; j++) { accC[i][j] = 0; accE[i][j] = 0; accX[i][j] = 0; }

    int lm = tid >> 2, q = tid & 3;
    int arow = row0 + lm; if (arow >= M) arow = M - 1;
    int kr = tid >> 4, cb = (tid & 15) * 8;

    for (int k0 = 0; k0 < C; k0 += 16) {
        float4 v;
        v = *(const float4*)&g_aggc[arow * C + k0 + q * 4];
        *(float4*)&sAc[lm][8 * q]     = make_float4(v.x, v.x, v.y, v.y);
        *(float4*)&sAc[lm][8 * q + 4] = make_float4(v.z, v.z, v.w, v.w);
        v = *(const float4*)&g_agge[arow * C + k0 + q * 4];
        *(float4*)&sAe[lm][8 * q]     = make_float4(v.x, v.x, v.y, v.y);
        *(float4*)&sAe[lm][8 * q + 4] = make_float4(v.z, v.z, v.w, v.w);
        v = *(const float4*)&X[arow * C + k0 + q * 4];
        *(float4*)&sAx[lm][8 * q]     = make_float4(v.x, v.x, v.y, v.y);
        *(float4*)&sAx[lm][8 * q + 4] = make_float4(v.z, v.z, v.w, v.w);
        *(float4*)&sBl[kr][cb]     = *(const float4*)&Wl[(k0 + kr) * C + cb];
        *(float4*)&sBl[kr][cb + 4] = *(const float4*)&Wl[(k0 + kr) * C + cb + 4];
        *(float4*)&sBr[kr][cb]     = *(const float4*)&Wr[(k0 + kr) * C + cb];
        *(float4*)&sBr[kr][cb + 4] = *(const float4*)&Wr[(k0 + kr) * C + cb + 4];
        __syncthreads();
        #pragma unroll
        for (int k = 0; k < 16; k++) {
            const u64* pl = (const u64*)&sBl[k][0];
            const u64* pr = (const u64*)&sBr[k][0];
            u64 bl[4], br[4];
            #pragma unroll
            for (int j = 0; j < 4; j++) { bl[j] = pl[tx + 16 * j]; br[j] = pr[tx + 16 * j]; }
            #pragma unroll
            for (int i = 0; i < 4; i++) {
                u64 a_c = *(const u64*)&sAc[(ty << 2) + i][2 * k];
                u64 a_e = *(const u64*)&sAe[(ty << 2) + i][2 * k];
                u64 a_x = *(const u64*)&sAx[(ty << 2) + i][2 * k];
                #pragma unroll
                for (int j = 0; j < 4; j++) {
                    ffma2(accC[i][j], a_c, bl[j]);
                    ffma2(accE[i][j], a_e, bl[j]);
                    ffma2(accX[i][j], a_x, br[j]);
                }
            }
        }
        __syncthreads();
    }
    #pragma unroll
    for (int i = 0; i < 4; i++) {
        int r = row0 + (ty << 2) + i;
        if (r < M) {
            #pragma unroll
            for (int j = 0; j < 4; j++) {
                int c0 = 2 * tx + 32 * j;
                float2 bb = *(const float2*)&bias[c0];
                float2 o3, o4;
                float xlo = lo32(accX[i][j]), xhi = hi32(accX[i][j]);
                o3.x = fmaxf(lo32(accC[i][j]) + xlo + bb.x, 0.f);
                o3.y = fmaxf(hi32(accC[i][j]) + xhi + bb.y, 0.f);
                o4.x = fmaxf(lo32(accE[i][j]) + xlo + bb.x, 0.f);
                o4.y = fmaxf(hi32(accE[i][j]) + xhi + bb.y, 0.f);
                *(float2*)&O3[r * C + c0] = o3;
                *(float2*)&O4[r * C + c0] = o4;
            }
        }
    }
}

// ---------------- layer 1: x1 = aggc@Wl + x3@Wr + b ; x2 = agge@Wl + x4@Wr + b ----------------
__global__ void layer1_kernel(const float* __restrict__ X3, const float* __restrict__ X4,
                              const float* __restrict__ Wl, const float* __restrict__ Wr,
                              const float* __restrict__ bias, int M) {
    __shared__ __align__(16) float sAc[64][36], sAe[64][36], sA3[64][36], sA4[64][36];
    __shared__ __align__(16) float sBl[16][128], sBr[16][128];
    int tid = threadIdx.x;
    int tx = tid & 15, ty = tid >> 4;
    int row0 = blockIdx.x * 64;
    u64 acc1[4][4], acc2[4][4];
    #pragma unroll
    for (int i = 0; i < 4; i++)
        #pragma unroll
        for (int j = 0; j < 4; j++) { acc1[i][j] = 0; acc2[i][j] = 0; }

    int lm = tid >> 2, q = tid & 3;
    int arow = row0 + lm; if (arow >= M) arow = M - 1;
    int kr = tid >> 4, cb = (tid & 15) * 8;

    for (int k0 = 0; k0 < C; k0 += 16) {
        float4 v;
        v = *(const float4*)&g_aggc[arow * C + k0 + q * 4];
        *(float4*)&sAc[lm][8 * q]     = make_float4(v.x, v.x, v.y, v.y);
        *(float4*)&sAc[lm][8 * q + 4] = make_float4(v.z, v.z, v.w, v.w);
        v = *(const float4*)&g_agge[arow * C + k0 + q * 4];
        *(float4*)&sAe[lm][8 * q]     = make_float4(v.x, v.x, v.y, v.y);
        *(float4*)&sAe[lm][8 * q + 4] = make_float4(v.z, v.z, v.w, v.w);
        v = *(const float4*)&X3[arow * C + k0 + q * 4];
        *(float4*)&sA3[lm][8 * q]     = make_float4(v.x, v.x, v.y, v.y);
        *(float4*)&sA3[lm][8 * q + 4] = make_float4(v.z, v.z, v.w, v.w);
        v = *(const float4*)&X4[arow * C + k0 + q * 4];
        *(float4*)&sA4[lm][8 * q]     = make_float4(v.x, v.x, v.y, v.y);
        *(float4*)&sA4[lm][8 * q + 4] = make_float4(v.z, v.z, v.w, v.w);
        *(float4*)&sBl[kr][cb]     = *(const float4*)&Wl[(k0 + kr) * C + cb];
        *(float4*)&sBl[kr][cb + 4] = *(const float4*)&Wl[(k0 + kr) * C + cb + 4];
        *(float4*)&sBr[kr][cb]     = *(const float4*)&Wr[(k0 + kr) * C + cb];
        *(float4*)&sBr[kr][cb + 4] = *(const float4*)&Wr[(k0 + kr) * C + cb + 4];
        __syncthreads();
        #pragma unroll
        for (int k = 0; k < 16; k++) {
            const u64* pl = (const u64*)&sBl[k][0];
            const u64* pr = (const u64*)&sBr[k][0];
            u64 bl[4], br[4];
            #pragma unroll
            for (int j = 0; j < 4; j++) { bl[j] = pl[tx + 16 * j]; br[j] = pr[tx + 16 * j]; }
            #pragma unroll
            for (int i = 0; i < 4; i++) {
                u64 a_c = *(const u64*)&sAc[(ty << 2) + i][2 * k];
                u64 a_e = *(const u64*)&sAe[(ty << 2) + i][2 * k];
                u64 a_3 = *(const u64*)&sA3[(ty << 2) + i][2 * k];
                u64 a_4 = *(const u64*)&sA4[(ty << 2) + i][2 * k];
                #pragma unroll
                for (int j = 0; j < 4; j++) {
                    ffma2(acc1[i][j], a_c, bl[j]);
                    ffma2(acc1[i][j], a_3, br[j]);
                    ffma2(acc2[i][j], a_e, bl[j]);
                    ffma2(acc2[i][j], a_4, br[j]);
                }
            }
        }
        __syncthreads();
    }
    #pragma unroll
    for (int i = 0; i < 4; i++) {
        int r = row0 + (ty << 2) + i;
        if (r < M) {
            #pragma unroll
            for (int j = 0; j < 4; j++) {
                int c0 = 2 * tx + 32 * j;
                float2 bb = *(const float2*)&bias[c0];
                float2 o1, o2;
                o1.x = lo32(acc1[i][j]) + bb.x;
                o1.y = hi32(acc1[i][j]) + bb.y;
                o2.x = lo32(acc2[i][j]) + bb.x;
                o2.y = hi32(acc2[i][j]) + bb.y;
                *(float2*)&g_x1[r * C + c0] = o1;
                *(float2*)&g_x2[r * C + c0] = o2;
            }
        }
    }
}

// ---------------- attention scores: s[r] = tanh(z_r@W1 + b1)@W2, r = node*4+branch ----------------
__global__ void score_kernel(const float* __restrict__ X3, const float* __restrict__ X4,
                             const float* __restrict__ W1, const float* __restrict__ b1,
                             const float* __restrict__ W2, int R) {
    __shared__ __align__(16) float sA[128][36];
    __shared__ __align__(16) float sB[16][64];
    int tid = threadIdx.x;
    int tx = tid & 7, ty = tid >> 3;
    int row0 = blockIdx.x * 128;
    u64 acc[4][4];
    #pragma unroll
    for (int i = 0; i < 4; i++)
        #pragma unroll
        for (int j = 0; j < 4; j++) acc[i][j] = 0;

    int lm = tid >> 1, h = tid & 1;
    int r = row0 + lm; if (r >= R) r = R - 1;
    int branch = r & 3, node = r >> 2;
    const float* zrow;
    if (branch == 0)      zrow = g_x1 + (size_t)node * C;
    else if (branch == 1) zrow = g_x2 + (size_t)node * C;
    else if (branch == 2) zrow = X3 + (size_t)node * C;
    else                  zrow = X4 + (size_t)node * C;
    int kr = tid >> 4, cb = (tid & 15) * 4;

    for (int k0 = 0; k0 < C; k0 += 16) {
        float4 v1 = *(const float4*)&zrow[k0 + 8 * h];
        float4 v2 = *(const float4*)&zrow[k0 + 8 * h + 4];
        *(float4*)&sA[lm][16 * h]      = make_float4(v1.x, v1.x, v1.y, v1.y);
        *(float4*)&sA[lm][16 * h + 4]  = make_float4(v1.z, v1.z, v1.w, v1.w);
        *(float4*)&sA[lm][16 * h + 8]  = make_float4(v2.x, v2.x, v2.y, v2.y);
        *(float4*)&sA[lm][16 * h + 12] = make_float4(v2.z, v2.z, v2.w, v2.w);
        *(float4*)&sB[kr][cb] = *(const float4*)&W1[(k0 + kr) * 64 + cb];
        __syncthreads();
        #pragma unroll
        for (int k = 0; k < 16; k++) {
            const u64* pb = (const u64*)&sB[k][0];
            u64 bl[4];
            #pragma unroll
            for (int j = 0; j < 4; j++) bl[j] = pb[tx + 8 * j];
            #pragma unroll
            for (int i = 0; i < 4; i++) {
                u64 a = *(const u64*)&sA[(ty << 2) + i][2 * k];
                #pragma unroll
                for (int j = 0; j < 4; j++) ffma2(acc[i][j], a, bl[j]);
            }
        }
        __syncthreads();
    }
    #pragma unroll
    for (int i = 0; i < 4; i++) {
        float s = 0.f;
        #pragma unroll
        for (int j = 0; j < 4; j++) {
            int c0 = 2 * tx + 16 * j;
            float2 bb = *(const float2*)&b1[c0];
            float2 w2 = *(const float2*)&W2[c0];
            s += tanhf(lo32(acc[i][j]) + bb.x) * w2.x;
            s += tanhf(hi32(acc[i][j]) + bb.y) * w2.y;
        }
        #pragma unroll
        for (int o = 4; o; o >>= 1) s += __shfl_xor_sync(0xffffffffu, s, o);
        if (tx == 0) {
            int rr = row0 + (ty << 2) + i;
            if (rr < R) g_scores[rr] = s;
        }
    }
}

// ---------------- softmax + weighted pooling ----------------
__global__ void pool_kernel(const float* __restrict__ X3, const float* __restrict__ X4,
                            float* __restrict__ emb, int N) {
    int node = blockIdx.x * 8 + (threadIdx.x >> 5);
    int lane = threadIdx.x & 31;
    if (node >= N) return;
    float s0 = g_scores[node * 4 + 0];
    float s1 = g_scores[node * 4 + 1];
    float s2 = g_scores[node * 4 + 2];
    float s3 = g_scores[node * 4 + 3];
    float m = fmaxf(fmaxf(s0, s1), fmaxf(s2, s3));
    float e0 = expf(s0 - m), e1 = expf(s1 - m), e2 = expf(s2 - m), e3 = expf(s3 - m);
    float inv = 1.0f / (e0 + e1 + e2 + e3);
    float b0 = e0 * inv, b1 = e1 * inv, b2 = e2 * inv, b3 = e3 * inv;
    float4 z1 = __ldg(&((const float4*)(g_x1 + (size_t)node * C))[lane]);
    float4 z2 = __ldg(&((const float4*)(g_x2 + (size_t)node * C))[lane]);
    float4 z3 = __ldg(&((const float4*)(X3 + (size_t)node * C))[lane]);
    float4 z4 = __ldg(&((const float4*)(X4 + (size_t)node * C))[lane]);
    float4 o;
    o.x = b0 * z1.x + b1 * z2.x + b2 * z3.x + b3 * z4.x;
    o.y = b0 * z1.y + b1 * z2.y + b2 * z3.y + b3 * z4.y;
    o.z = b0 * z1.z + b1 * z2.z + b2 * z3.z + b3 * z4.z;
    o.w = b0 * z1.w + b1 * z2.w + b2 * z3.w + b3 * z4.w;
    ((float4*)(emb + (size_t)node * C))[lane] = o;
}

// ---------------- launch ----------------
extern "C" void kernel_launch(void* const* d_in, const int* in_sizes, int n_in,
                              void* d_out, int out_size) {
    const float* x   = (const float*)d_in[0];
    const int*   row = (const int*)d_in[1];
    const int*   col = (const int*)d_in[2];
    const float* Wl0 = (const float*)d_in[3];
    const float* bl0 = (const float*)d_in[4];
    const float* Wr0 = (const float*)d_in[5];
    const float* Wl1 = (const float*)d_in[6];
    const float* bl1 = (const float*)d_in[7];
    const float* Wr1 = (const float*)d_in[8];
    const float* aW1 = (const float*)d_in[9];
    const float* ab1 = (const float*)d_in[10];
    const float* aW2 = (const float*)d_in[11];

    int N = in_sizes[0] / C;
    int E = in_sizes[1];

    float* emb = (float*)d_out;
    float* x3o = emb + (size_t)N * C;
    float* x4o = x3o + (size_t)N * C;

    int nb8 = (N + 7) / 8;
    int nbE = (E + 255) / 256;
    int nbM = (N + 63) / 64;
    int nbS = (4 * N + 127) / 128;

    zero_cnt_kernel<<<(N + 255) / 256, 256>>>(N);
    hist_kernel<<<nbE, 256>>>(row, E);
    scan_kernel<<<1, 1024>>>(N);
    fill_kernel<<<nbE, 256>>>(row, col, E);

    norm1_kernel<<<nb8, 256>>>(x, N);
    edge1_kernel<<<nb8, 256>>>(x, N);
    layer0_kernel<<<nbM, 256>>>(x, Wl0, Wr0, bl0, x3o, x4o, N);

    norm2_kernel<<<nb8, 256>>>(x3o, x4o, N);
    edge2_kernel<<<nb8, 256>>>(x3o, x4o, N);
    layer1_kernel<<<nbM, 256>>>(x3o, x4o, Wl1, Wr1, bl1, N);

    score_kernel<<<nbS, 256>>>(x3o, x4o, aW1, ab1, aW2, 4 * N);
    pool_kernel<<<nb8, 256>>>(x3o, x4o, emb, N);
}

// round 17
// speedup vs baseline: 1.0504x; 1.0504x over previous
#include <cuda_runtime.h>
#include <math.h>

typedef unsigned long long u64;

#define NMAX 50000
#define EMAX 800000
#define C 128

// ---------------- scratch (static __device__, no allocation) ----------------
__device__ int    g_cnt [NMAX];
__device__ int    g_fill[NMAX];
__device__ int    g_ptr [NMAX + 1];
__device__ int    g_ecol[EMAX];
__device__ float4 g_nn  [NMAX];        // {n_cos, q_eud, p_eud, 0}
__device__ float  g_aggc[NMAX * C];
__device__ float  g_agge[NMAX * C];
__device__ float  g_x1  [NMAX * C];
__device__ float  g_x2  [NMAX * C];
__device__ float  g_scores[NMAX * 4];

// ---------------- packed fp32x2 helpers (SASS FFMA2) ----------------
__device__ __forceinline__ void ffma2(u64& d, u64 a, u64 b) {
    asm("fma.rn.f32x2 %0, %1, %2, %0;" : "+l"(d) : "l"(a), "l"(b));
}
__device__ __forceinline__ float lo32(u64 v) { return __uint_as_float((unsigned)v); }
__device__ __forceinline__ float hi32(u64 v) { return __uint_as_float((unsigned)(v >> 32)); }

// ---------------- CSR build ----------------
__global__ void zero_cnt_kernel(int N) {
    int i = blockIdx.x * blockDim.x + threadIdx.x;
    if (i < N) g_cnt[i] = 0;
}

__global__ void hist_kernel(const int* __restrict__ row, int E) {
    int i = blockIdx.x * blockDim.x + threadIdx.x;
    if (i < E) atomicAdd(&g_cnt[row[i]], 1);
}

__global__ void scan_kernel(int N) {
    __shared__ int sums[1024];
    int t = threadIdx.x;
    int chunk = (N + 1023) >> 10;
    int start = t * chunk;
    int end = min(start + chunk, N);
    int s = 0;
    for (int i = start; i < end; i++) s += g_cnt[i];
    sums[t] = s;
    __syncthreads();
    for (int off = 1; off < 1024; off <<= 1) {
        int v = (t >= off) ? sums[t - off] : 0;
        __syncthreads();
        sums[t] += v;
        __syncthreads();
    }
    int base = sums[t] - s;
    for (int i = start; i < end; i++) {
        g_ptr[i]  = base;
        g_fill[i] = base;
        base += g_cnt[i];
    }
    if (t == 0) g_ptr[N] = sums[1023];
}

__global__ void fill_kernel(const int* __restrict__ row, const int* __restrict__ col, int E) {
    int i = blockIdx.x * blockDim.x + threadIdx.x;
    if (i < E) {
        int r = row[i];
        int p = atomicAdd(&g_fill[r], 1);
        g_ecol[p] = col[i];
    }
}

// ---------------- per-node stats: {n(cos), q=ss-2*eps*sum, p=ss+2*eps*sum} ----------------
__global__ void norm1_kernel(const float* __restrict__ X, int N) {
    int node = blockIdx.x * 8 + (threadIdx.x >> 5);
    int lane = threadIdx.x & 31;
    if (node >= N) return;
    float4 v = ((const float4*)X)[node * 32 + lane];
    float ss = v.x * v.x + v.y * v.y + v.z * v.z + v.w * v.w;
    float sm = v.x + v.y + v.z + v.w;
    #pragma unroll
    for (int o = 16; o; o >>= 1) {
        ss += __shfl_xor_sync(0xffffffffu, ss, o);
        sm += __shfl_xor_sync(0xffffffffu, sm, o);
    }
    if (lane == 0)
        g_nn[node] = make_float4(sqrtf(ss), ss - 2e-6f * sm, ss + 2e-6f * sm, 0.f);
}

__global__ void norm2_kernel(const float* __restrict__ X3, const float* __restrict__ X4, int N) {
    int node = blockIdx.x * 8 + (threadIdx.x >> 5);
    int lane = threadIdx.x & 31;
    if (node >= N) return;
    float4 a = ((const float4*)X3)[node * 32 + lane];
    float4 b = ((const float4*)X4)[node * 32 + lane];
    float s3 = a.x * a.x + a.y * a.y + a.z * a.z + a.w * a.w;
    float s4 = b.x * b.x + b.y * b.y + b.z * b.z + b.w * b.w;
    float m4 = b.x + b.y + b.z + b.w;
    #pragma unroll
    for (int o = 16; o; o >>= 1) {
        s3 += __shfl_xor_sync(0xffffffffu, s3, o);
        s4 += __shfl_xor_sync(0xffffffffu, s4, o);
        m4 += __shfl_xor_sync(0xffffffffu, m4, o);
    }
    if (lane == 0)
        g_nn[node] = make_float4(sqrtf(s3), s4 - 2e-6f * m4, s4 + 2e-6f * m4, 0.f);
}

// ---------------- edge pass 1 (R7 control flow, single reduction via eud identity) ----------------
__global__ void edge1_kernel(const float* __restrict__ X, int N) {
    int node = blockIdx.x * 8 + (threadIdx.x >> 5);
    int lane = threadIdx.x & 31;
    if (node >= N) return;
    const float4* X4 = (const float4*)X;
    float4 xi = X4[node * 32 + lane];
    float4 me = g_nn[node];
    float ni = me.x, pi = me.z;
    int s = g_ptr[node], e = g_ptr[node + 1];
    float4 ac = make_float4(0.f, 0.f, 0.f, 0.f);
    float4 ae = make_float4(0.f, 0.f, 0.f, 0.f);
    int cNext = (s < e) ? __ldg(&g_ecol[s]) : 0;
    for (int j = s; j < e; j++) {
        int c = cNext;
        if (j + 1 < e) cNext = __ldg(&g_ecol[j + 1]);
        float4 xc = __ldg(&X4[c * 32 + lane]);
        float2 nq = __ldg((const float2*)&g_nn[c]);
        float d = xi.x * xc.x + xi.y * xc.y + xi.z * xc.z + xi.w * xc.w;
        #pragma unroll
        for (int o = 16; o; o >>= 1) d += __shfl_xor_sync(0xffffffffu, d, o);
        float ecos = d / fmaxf(ni * nq.x, 1e-8f);
        float eeud = sqrtf(fmaxf(pi + nq.y - 2.f * d + 1.28e-10f, 0.f));
        ac.x += ecos * xc.x; ac.y += ecos * xc.y; ac.z += ecos * xc.z; ac.w += ecos * xc.w;
        ae.x += eeud * xc.x; ae.y += eeud * xc.y; ae.z += eeud * xc.z; ae.w += eeud * xc.w;
    }
    float inv = 1.0f / fmaxf((float)(e - s), 1.0f);
    ac.x *= inv; ac.y *= inv; ac.z *= inv; ac.w *= inv;
    ae.x *= inv; ae.y *= inv; ae.z *= inv; ae.w *= inv;
    ((float4*)g_aggc)[node * 32 + lane] = ac;
    ((float4*)g_agge)[node * 32 + lane] = ae;
}

// ---------------- edge pass 2 (R7 control flow, eud in dot-form) ----------------
__global__ void edge2_kernel(const float* __restrict__ X3, const float* __restrict__ X4, int N) {
    int node = blockIdx.x * 8 + (threadIdx.x >> 5);
    int lane = threadIdx.x & 31;
    if (node >= N) return;
    const float4* A4 = (const float4*)X3;
    const float4* B4 = (const float4*)X4;
    float4 x3i = A4[node * 32 + lane];
    float4 x4i = B4[node * 32 + lane];
    float4 me = g_nn[node];
    float n3 = me.x, p4 = me.z;
    int s = g_ptr[node], e = g_ptr[node + 1];
    float4 ac = make_float4(0.f, 0.f, 0.f, 0.f);
    float4 ae = make_float4(0.f, 0.f, 0.f, 0.f);
    int cNext = (s < e) ? __ldg(&g_ecol[s]) : 0;
    for (int j = s; j < e; j++) {
        int c = cNext;
        if (j + 1 < e) cNext = __ldg(&g_ecol[j + 1]);
        float4 xc3 = __ldg(&A4[c * 32 + lane]);
        float4 xc4 = __ldg(&B4[c * 32 + lane]);
        float2 nq = __ldg((const float2*)&g_nn[c]);
        float d3 = x3i.x * xc3.x + x3i.y * xc3.y + x3i.z * xc3.z + x3i.w * xc3.w;
        float d4 = x4i.x * xc4.x + x4i.y * xc4.y + x4i.z * xc4.z + x4i.w * xc4.w;
        #pragma unroll
        for (int o = 16; o; o >>= 1) {
            d3 += __shfl_xor_sync(0xffffffffu, d3, o);
            d4 += __shfl_xor_sync(0xffffffffu, d4, o);
        }
        float ecos = d3 / fmaxf(n3 * nq.x, 1e-8f);
        float eeud = sqrtf(fmaxf(p4 + nq.y - 2.f * d4 + 1.28e-10f, 0.f));
        ac.x += ecos * xc3.x; ac.y += ecos * xc3.y; ac.z += ecos * xc3.z; ac.w += ecos * xc3.w;
        ae.x += eeud * xc4.x; ae.y += eeud * xc4.y; ae.z += eeud * xc4.z; ae.w += eeud * xc4.w;
    }
    float inv = 1.0f / fmaxf((float)(e - s), 1.0f);
    ac.x *= inv; ac.y *= inv; ac.z *= inv; ac.w *= inv;
    ae.x *= inv; ae.y *= inv; ae.z *= inv; ae.w *= inv;
    ((float4*)g_aggc)[node * 32 + lane] = ac;
    ((float4*)g_agge)[node * 32 + lane] = ae;
}

// ==================== GEMM kernels (unchanged from R7) ====================

// ---------------- layer 0: x3 = relu(aggc@Wl + x@Wr + b), x4 = relu(agge@Wl + x@Wr + b) ----------------
__global__ void layer0_kernel(const float* __restrict__ X,
                              const float* __restrict__ Wl, const float* __restrict__ Wr,
                              const float* __restrict__ bias,
                              float* __restrict__ O3, float* __restrict__ O4, int M) {
    __shared__ __align__(16) float sAc[64][36], sAe[64][36], sAx[64][36];
    __shared__ __align__(16) float sBl[16][128], sBr[16][128];
    int tid = threadIdx.x;
    int tx = tid & 15, ty = tid >> 4;
    int row0 = blockIdx.x * 64;
    u64 accC[4][4], accE[4][4], accX[4][4];
    #pragma unroll
    for (int i = 0; i < 4; i++)
        #pragma unroll
        for (int j = 0; j < 4; j++) { accC[i][j] = 0; accE[i][j] = 0; accX[i][j] = 0; }

    int lm = tid >> 2, q = tid & 3;
    int arow = row0 + lm; if (arow >= M) arow = M - 1;
    int kr = tid >> 4, cb = (tid & 15) * 8;

    for (int k0 = 0; k0 < C; k0 += 16) {
        float4 v;
        v = *(const float4*)&g_aggc[arow * C + k0 + q * 4];
        *(float4*)&sAc[lm][8 * q]     = make_float4(v.x, v.x, v.y, v.y);
        *(float4*)&sAc[lm][8 * q + 4] = make_float4(v.z, v.z, v.w, v.w);
        v = *(const float4*)&g_agge[arow * C + k0 + q * 4];
        *(float4*)&sAe[lm][8 * q]     = make_float4(v.x, v.x, v.y, v.y);
        *(float4*)&sAe[lm][8 * q + 4] = make_float4(v.z, v.z, v.w, v.w);
        v = *(const float4*)&X[arow * C + k0 + q * 4];
        *(float4*)&sAx[lm][8 * q]     = make_float4(v.x, v.x, v.y, v.y);
        *(float4*)&sAx[lm][8 * q + 4] = make_float4(v.z, v.z, v.w, v.w);
        *(float4*)&sBl[kr][cb]     = *(const float4*)&Wl[(k0 + kr) * C + cb];
        *(float4*)&sBl[kr][cb + 4] = *(const float4*)&Wl[(k0 + kr) * C + cb + 4];
        *(float4*)&sBr[kr][cb]     = *(const float4*)&Wr[(k0 + kr) * C + cb];
        *(float4*)&sBr[kr][cb + 4] = *(const float4*)&Wr[(k0 + kr) * C + cb + 4];
        __syncthreads();
        #pragma unroll
        for (int k = 0; k < 16; k++) {
            const u64* pl = (const u64*)&sBl[k][0];
            const u64* pr = (const u64*)&sBr[k][0];
            u64 bl[4], br[4];
            #pragma unroll
            for (int j = 0; j < 4; j++) { bl[j] = pl[tx + 16 * j]; br[j] = pr[tx + 16 * j]; }
            #pragma unroll
            for (int i = 0; i < 4; i++) {
                u64 a_c = *(const u64*)&sAc[(ty << 2) + i][2 * k];
                u64 a_e = *(const u64*)&sAe[(ty << 2) + i][2 * k];
                u64 a_x = *(const u64*)&sAx[(ty << 2) + i][2 * k];
                #pragma unroll
                for (int j = 0; j < 4; j++) {
                    ffma2(accC[i][j], a_c, bl[j]);
                    ffma2(accE[i][j], a_e, bl[j]);
                    ffma2(accX[i][j], a_x, br[j]);
                }
            }
        }
        __syncthreads();
    }
    #pragma unroll
    for (int i = 0; i < 4; i++) {
        int r = row0 + (ty << 2) + i;
        if (r < M) {
            #pragma unroll
            for (int j = 0; j < 4; j++) {
                int c0 = 2 * tx + 32 * j;
                float2 bb = *(const float2*)&bias[c0];
                float2 o3, o4;
                float xlo = lo32(accX[i][j]), xhi = hi32(accX[i][j]);
                o3.x = fmaxf(lo32(accC[i][j]) + xlo + bb.x, 0.f);
                o3.y = fmaxf(hi32(accC[i][j]) + xhi + bb.y, 0.f);
                o4.x = fmaxf(lo32(accE[i][j]) + xlo + bb.x, 0.f);
                o4.y = fmaxf(hi32(accE[i][j]) + xhi + bb.y, 0.f);
                *(float2*)&O3[r * C + c0] = o3;
                *(float2*)&O4[r * C + c0] = o4;
            }
        }
    }
}

// ---------------- layer 1: x1 = aggc@Wl + x3@Wr + b ; x2 = agge@Wl + x4@Wr + b ----------------
__global__ void layer1_kernel(const float* __restrict__ X3, const float* __restrict__ X4,
                              const float* __restrict__ Wl, const float* __restrict__ Wr,
                              const float* __restrict__ bias, int M) {
    __shared__ __align__(16) float sAc[64][36], sAe[64][36], sA3[64][36], sA4[64][36];
    __shared__ __align__(16) float sBl[16][128], sBr[16][128];
    int tid = threadIdx.x;
    int tx = tid & 15, ty = tid >> 4;
    int row0 = blockIdx.x * 64;
    u64 acc1[4][4], acc2[4][4];
    #pragma unroll
    for (int i = 0; i < 4; i++)
        #pragma unroll
        for (int j = 0; j < 4; j++) { acc1[i][j] = 0; acc2[i][j] = 0; }

    int lm = tid >> 2, q = tid & 3;
    int arow = row0 + lm; if (arow >= M) arow = M - 1;
    int kr = tid >> 4, cb = (tid & 15) * 8;

    for (int k0 = 0; k0 < C; k0 += 16) {
        float4 v;
        v = *(const float4*)&g_aggc[arow * C + k0 + q * 4];
        *(float4*)&sAc[lm][8 * q]     = make_float4(v.x, v.x, v.y, v.y);
        *(float4*)&sAc[lm][8 * q + 4] = make_float4(v.z, v.z, v.w, v.w);
        v = *(const float4*)&g_agge[arow * C + k0 + q * 4];
        *(float4*)&sAe[lm][8 * q]     = make_float4(v.x, v.x, v.y, v.y);
        *(float4*)&sAe[lm][8 * q + 4] = make_float4(v.z, v.z, v.w, v.w);
        v = *(const float4*)&X3[arow * C + k0 + q * 4];
        *(float4*)&sA3[lm][8 * q]     = make_float4(v.x, v.x, v.y, v.y);
        *(float4*)&sA3[lm][8 * q + 4] = make_float4(v.z, v.z, v.w, v.w);
        v = *(const float4*)&X4[arow * C + k0 + q * 4];
        *(float4*)&sA4[lm][8 * q]     = make_float4(v.x, v.x, v.y, v.y);
        *(float4*)&sA4[lm][8 * q + 4] = make_float4(v.z, v.z, v.w, v.w);
        *(float4*)&sBl[kr][cb]     = *(const float4*)&Wl[(k0 + kr) * C + cb];
        *(float4*)&sBl[kr][cb + 4] = *(const float4*)&Wl[(k0 + kr) * C + cb + 4];
        *(float4*)&sBr[kr][cb]     = *(const float4*)&Wr[(k0 + kr) * C + cb];
        *(float4*)&sBr[kr][cb + 4] = *(const float4*)&Wr[(k0 + kr) * C + cb + 4];
        __syncthreads();
        #pragma unroll
        for (int k = 0; k < 16; k++) {
            const u64* pl = (const u64*)&sBl[k][0];
            const u64* pr = (const u64*)&sBr[k][0];
            u64 bl[4], br[4];
            #pragma unroll
            for (int j = 0; j < 4; j++) { bl[j] = pl[tx + 16 * j]; br[j] = pr[tx + 16 * j]; }
            #pragma unroll
            for (int i = 0; i < 4; i++) {
                u64 a_c = *(const u64*)&sAc[(ty << 2) + i][2 * k];
                u64 a_e = *(const u64*)&sAe[(ty << 2) + i][2 * k];
                u64 a_3 = *(const u64*)&sA3[(ty << 2) + i][2 * k];
                u64 a_4 = *(const u64*)&sA4[(ty << 2) + i][2 * k];
                #pragma unroll
                for (int j = 0; j < 4; j++) {
                    ffma2(acc1[i][j], a_c, bl[j]);
                    ffma2(acc1[i][j], a_3, br[j]);
                    ffma2(acc2[i][j], a_e, bl[j]);
                    ffma2(acc2[i][j], a_4, br[j]);
                }
            }
        }
        __syncthreads();
    }
    #pragma unroll
    for (int i = 0; i < 4; i++) {
        int r = row0 + (ty << 2) + i;
        if (r < M) {
            #pragma unroll
            for (int j = 0; j < 4; j++) {
                int c0 = 2 * tx + 32 * j;
                float2 bb = *(const float2*)&bias[c0];
                float2 o1, o2;
                o1.x = lo32(acc1[i][j]) + bb.x;
                o1.y = hi32(acc1[i][j]) + bb.y;
                o2.x = lo32(acc2[i][j]) + bb.x;
                o2.y = hi32(acc2[i][j]) + bb.y;
                *(float2*)&g_x1[r * C + c0] = o1;
                *(float2*)&g_x2[r * C + c0] = o2;
            }
        }
    }
}

// ---------------- attention scores: s[r] = tanh(z_r@W1 + b1)@W2, r = node*4+branch ----------------
__global__ void score_kernel(const float* __restrict__ X3, const float* __restrict__ X4,
                             const float* __restrict__ W1, const float* __restrict__ b1,
                             const float* __restrict__ W2, int R) {
    __shared__ __align__(16) float sA[128][36];
    __shared__ __align__(16) float sB[16][64];
    int tid = threadIdx.x;
    int tx = tid & 7, ty = tid >> 3;
    int row0 = blockIdx.x * 128;
    u64 acc[4][4];
    #pragma unroll
    for (int i = 0; i < 4; i++)
        #pragma unroll
        for (int j = 0; j < 4; j++) acc[i][j] = 0;

    int lm = tid >> 1, h = tid & 1;
    int r = row0 + lm; if (r >= R) r = R - 1;
    int branch = r & 3, node = r >> 2;
    const float* zrow;
    if (branch == 0)      zrow = g_x1 + (size_t)node * C;
    else if (branch == 1) zrow = g_x2 + (size_t)node * C;
    else if (branch == 2) zrow = X3 + (size_t)node * C;
    else                  zrow = X4 + (size_t)node * C;
    int kr = tid >> 4, cb = (tid & 15) * 4;

    for (int k0 = 0; k0 < C; k0 += 16) {
        float4 v1 = *(const float4*)&zrow[k0 + 8 * h];
        float4 v2 = *(const float4*)&zrow[k0 + 8 * h + 4];
        *(float4*)&sA[lm][16 * h]      = make_float4(v1.x, v1.x, v1.y, v1.y);
        *(float4*)&sA[lm][16 * h + 4]  = make_float4(v1.z, v1.z, v1.w, v1.w);
        *(float4*)&sA[lm][16 * h + 8]  = make_float4(v2.x, v2.x, v2.y, v2.y);
        *(float4*)&sA[lm][16 * h + 12] = make_float4(v2.z, v2.z, v2.w, v2.w);
        *(float4*)&sB[kr][cb] = *(const float4*)&W1[(k0 + kr) * 64 + cb];
        __syncthreads();
        #pragma unroll
        for (int k = 0; k < 16; k++) {
            const u64* pb = (const u64*)&sB[k][0];
            u64 bl[4];
            #pragma unroll
            for (int j = 0; j < 4; j++) bl[j] = pb[tx + 8 * j];
            #pragma unroll
            for (int i = 0; i < 4; i++) {
                u64 a = *(const u64*)&sA[(ty << 2) + i][2 * k];
                #pragma unroll
                for (int j = 0; j < 4; j++) ffma2(acc[i][j], a, bl[j]);
            }
        }
        __syncthreads();
    }
    #pragma unroll
    for (int i = 0; i < 4; i++) {
        float s = 0.f;
        #pragma unroll
        for (int j = 0; j < 4; j++) {
            int c0 = 2 * tx + 16 * j;
            float2 bb = *(const float2*)&b1[c0];
            float2 w2 = *(const float2*)&W2[c0];
            s += tanhf(lo32(acc[i][j]) + bb.x) * w2.x;
            s += tanhf(hi32(acc[i][j]) + bb.y) * w2.y;
        }
        #pragma unroll
        for (int o = 4; o; o >>= 1) s += __shfl_xor_sync(0xffffffffu, s, o);
        if (tx == 0) {
            int rr = row0 + (ty << 2) + i;
            if (rr < R) g_scores[rr] = s;
        }
    }
}

// ---------------- softmax + weighted pooling ----------------
__global__ void pool_kernel(const float* __restrict__ X3, const float* __restrict__ X4,
                            float* __restrict__ emb, int N) {
    int node = blockIdx.x * 8 + (threadIdx.x >> 5);
    int lane = threadIdx.x & 31;
    if (node >= N) return;
    float s0 = g_scores[node * 4 + 0];
    float s1 = g_scores[node * 4 + 1];
    float s2 = g_scores[node * 4 + 2];
    float s3 = g_scores[node * 4 + 3];
    float m = fmaxf(fmaxf(s0, s1), fmaxf(s2, s3));
    float e0 = expf(s0 - m), e1 = expf(s1 - m), e2 = expf(s2 - m), e3 = expf(s3 - m);
    float inv = 1.0f / (e0 + e1 + e2 + e3);
    float b0 = e0 * inv, b1 = e1 * inv, b2 = e2 * inv, b3 = e3 * inv;
    float4 z1 = __ldg(&((const float4*)(g_x1 + (size_t)node * C))[lane]);
    float4 z2 = __ldg(&((const float4*)(g_x2 + (size_t)node * C))[lane]);
    float4 z3 = __ldg(&((const float4*)(X3 + (size_t)node * C))[lane]);
    float4 z4 = __ldg(&((const float4*)(X4 + (size_t)node * C))[lane]);
    float4 o;
    o.x = b0 * z1.x + b1 * z2.x + b2 * z3.x + b3 * z4.x;
    o.y = b0 * z1.y + b1 * z2.y + b2 * z3.y + b3 * z4.y;
    o.z = b0 * z1.z + b1 * z2.z + b2 * z3.z + b3 * z4.z;
    o.w = b0 * z1.w + b1 * z2.w + b2 * z3.w + b3 * z4.w;
    ((float4*)(emb + (size_t)node * C))[lane] = o;
}

// ---------------- launch ----------------
extern "C" void kernel_launch(void* const* d_in, const int* in_sizes, int n_in,
                              void* d_out, int out_size) {
    const float* x   = (const float*)d_in[0];
    const int*   row = (const int*)d_in[1];
    const int*   col = (const int*)d_in[2];
    const float* Wl0 = (const float*)d_in[3];
    const float* bl0 = (const float*)d_in[4];
    const float* Wr0 = (const float*)d_in[5];
    const float* Wl1 = (const float*)d_in[6];
    const float* bl1 = (const float*)d_in[7];
    const float* Wr1 = (const float*)d_in[8];
    const float* aW1 = (const float*)d_in[9];
    const float* ab1 = (const float*)d_in[10];
    const float* aW2 = (const float*)d_in[11];

    int N = in_sizes[0] / C;
    int E = in_sizes[1];

    float* emb = (float*)d_out;
    float* x3o = emb + (size_t)N * C;
    float* x4o = x3o + (size_t)N * C;

    int nb8 = (N + 7) / 8;
    int nbE = (E + 255) / 256;
    int nbM = (N + 63) / 64;
    int nbS = (4 * N + 127) / 128;

    zero_cnt_kernel<<<(N + 255) / 256, 256>>>(N);
    hist_kernel<<<nbE, 256>>>(row, E);
    scan_kernel<<<1, 1024>>>(N);
    fill_kernel<<<nbE, 256>>>(row, col, E);

    norm1_kernel<<<nb8, 256>>>(x, N);
    edge1_kernel<<<nb8, 256>>>(x, N);
    layer0_kernel<<<nbM, 256>>>(x, Wl0, Wr0, bl0, x3o, x4o, N);

    norm2_kernel<<<nb8, 256>>>(x3o, x4o, N);
    edge2_kernel<<<nb8, 256>>>(x3o, x4o, N);
    layer1_kernel<<<nbM, 256>>>(x3o, x4o, Wl1, Wr1, bl1, N);

    score_kernel<<<nbS, 256>>>(x3o, x4o, aW1, ab1, aW2, 4 * N);
    pool_kernel<<<nb8, 256>>>(x3o, x4o, emb, N);
}